// round 4
// baseline (speedup 1.0000x reference)
#include <cuda_runtime.h>

typedef unsigned long long ull;

#define T_STEPS 2048
#define B_ROWS  256
#define HID     128
#define NG      512

// ---------------- scratch (device globals: allocation-free) ----------------
__device__ float g_hseq[(size_t)T_STEPS * B_ROWS * HID];   // 256 MB
__device__ float g_xg[(size_t)T_STEPS * B_ROWS * NG];      // 1 GB
__device__ float g_hT[B_ROWS * HID];

// ---------------- packed f32x2 helpers (sm_100+) ----------------
__device__ __forceinline__ ull pk2(float lo, float hi){
    ull r; asm("mov.b64 %0,{%1,%2};" : "=l"(r) : "f"(lo), "f"(hi)); return r;
}
__device__ __forceinline__ ull ffma2(ull a, ull b, ull c){
    ull d; asm("fma.rn.f32x2 %0,%1,%2,%3;" : "=l"(d) : "l"(a), "l"(b), "l"(c)); return d;
}
__device__ __forceinline__ float2 unpk(ull v){
    float2 r; asm("mov.b64 {%0,%1},%2;" : "=f"(r.x), "=f"(r.y) : "l"(v)); return r;
}
__device__ __forceinline__ float sigf(float x){
    return __fdividef(1.f, 1.f + __expf(-x));
}
__device__ __forceinline__ float tanhf_(float x){
    // 1 - 2/(exp(2x)+1): exact at +/-inf, ~1e-6 rel err
    return 1.f - 2.f * __fdividef(1.f, __expf(2.f * x) + 1.f);
}

// ---------------- recurrent kernel ----------------
// 128 CTAs x 256 threads. CTA b owns batch rows 2b, 2b+1.
// Thread tid owns gate rows j0=tid (i or f) and j1=tid+256 (g or o).
// Whh cols [0,80) in registers (40 f32x2 per row), cols [80,128) in SMEM.
constexpr int KREGP = 40;                 // f32x2 pairs per gate row in regs
constexpr int KSM4  = 12;                 // float4 tail chunks per row in smem
constexpr int REC_SMEM = (KSM4*NG*4 + 2*HID + 2*NG) * 4;   // 103424 B

// MODE 0: layer0 (scalar input folded in, writes hseq)
// MODE 1: mid layer (reads g_xg, writes hseq)
// MODE 2: last layer (reads g_xg, writes only g_hT at t=T-1)
template<int MODE>
__global__ void __launch_bounds__(256, 1)
lstm_rec(const float* __restrict__ xin,   // MODE0: x (B,T,1)
         const float* __restrict__ wih,   // MODE0: Wih0 (512,1)
         const float* __restrict__ bih,   // MODE0 biases
         const float* __restrict__ bhh,
         const float* __restrict__ Whh)   // (512,128)
{
    extern __shared__ float sm[];
    float4* ws = (float4*)sm;             // [KSM4][NG] weight tail
    float*  sh = sm + KSM4*NG*4;          // [2][HID] hidden state
    float*  sg = sh + 2*HID;              // [2][NG]  activated gates

    const int tid = threadIdx.x;
    const int j0 = tid, j1 = tid + 256;
    const int r0 = blockIdx.x * 2;

    // one-time weight load: 80 cols -> regs, 48 cols -> smem
    ull w0[KREGP], w1[KREGP];
    {
        const float* p0 = Whh + (size_t)j0 * HID;
        const float* p1 = Whh + (size_t)j1 * HID;
        #pragma unroll
        for (int p = 0; p < KREGP; p++){
            w0[p] = *(const ull*)(p0 + 2*p);
            w1[p] = *(const ull*)(p1 + 2*p);
        }
        #pragma unroll
        for (int q = 0; q < KSM4; q++){
            ws[q*NG + j0] = *(const float4*)(p0 + 2*KREGP + 4*q);
            ws[q*NG + j1] = *(const float4*)(p1 + 2*KREGP + 4*q);
        }
    }
    float wi0 = 0.f, wi1 = 0.f, bb0 = 0.f, bb1 = 0.f;
    if (MODE == 0){
        wi0 = wih[j0]; wi1 = wih[j1];
        bb0 = bih[j0] + bhh[j0]; bb1 = bih[j1] + bhh[j1];
    }
    if (tid < HID){ sh[tid] = 0.f; sh[HID + tid] = 0.f; }
    float c0 = 0.f, c1 = 0.f;
    __syncthreads();

    for (int t = 0; t < T_STEPS; t++){
        // input-projection contribution (issued early; consumed after dot product)
        float in00, in01, in10, in11;
        if (MODE == 0){
            float xv0 = __ldg(xin + (size_t)r0 * T_STEPS + t);
            float xv1 = __ldg(xin + (size_t)(r0+1) * T_STEPS + t);
            in00 = fmaf(xv0, wi0, bb0); in01 = fmaf(xv1, wi0, bb0);
            in10 = fmaf(xv0, wi1, bb1); in11 = fmaf(xv1, wi1, bb1);
        } else {
            const float* xg = g_xg + ((size_t)t * B_ROWS + r0) * NG;
            in00 = __ldg(xg + j0);      in10 = __ldg(xg + j1);
            in01 = __ldg(xg + NG + j0); in11 = __ldg(xg + NG + j1);
        }
        ull a00 = pk2(in00, 0.f), a01 = pk2(in01, 0.f);
        ull a10 = pk2(in10, 0.f), a11 = pk2(in11, 0.f);

        const ulonglong2* h0 = (const ulonglong2*)sh;        // batch r0 pairs
        const ulonglong2* h1 = (const ulonglong2*)(sh + HID);// batch r1 pairs
        #pragma unroll
        for (int p = 0; p < KREGP/2; p++){
            ulonglong2 hp0 = h0[p], hp1 = h1[p];
            a00 = ffma2(w0[2*p],   hp0.x, a00);
            a00 = ffma2(w0[2*p+1], hp0.y, a00);
            a01 = ffma2(w0[2*p],   hp1.x, a01);
            a01 = ffma2(w0[2*p+1], hp1.y, a01);
            a10 = ffma2(w1[2*p],   hp0.x, a10);
            a10 = ffma2(w1[2*p+1], hp0.y, a10);
            a11 = ffma2(w1[2*p],   hp1.x, a11);
            a11 = ffma2(w1[2*p+1], hp1.y, a11);
        }
        #pragma unroll
        for (int q = 0; q < KSM4; q++){
            float4 v0 = ws[q*NG + j0];
            float4 v1 = ws[q*NG + j1];
            ulonglong2 hq0 = h0[KREGP/2 + q];
            ulonglong2 hq1 = h1[KREGP/2 + q];
            ull w0a = pk2(v0.x, v0.y), w0b = pk2(v0.z, v0.w);
            ull w1a = pk2(v1.x, v1.y), w1b = pk2(v1.z, v1.w);
            a00 = ffma2(w0a, hq0.x, a00); a00 = ffma2(w0b, hq0.y, a00);
            a01 = ffma2(w0a, hq1.x, a01); a01 = ffma2(w0b, hq1.y, a01);
            a10 = ffma2(w1a, hq0.x, a10); a10 = ffma2(w1b, hq0.y, a10);
            a11 = ffma2(w1a, hq1.x, a11); a11 = ffma2(w1b, hq1.y, a11);
        }
        float2 f00 = unpk(a00), f01 = unpk(a01), f10 = unpk(a10), f11 = unpk(a11);
        float g00 = f00.x + f00.y, g01 = f01.x + f01.y;
        float g10 = f10.x + f10.y, g11 = f11.x + f11.y;
        // j0 in [0,256): i or f -> sigmoid. j1: tid<128 -> g (tanh), else o (sigmoid)
        g00 = sigf(g00); g01 = sigf(g01);
        if (tid < 128){ g10 = tanhf_(g10); g11 = tanhf_(g11); }
        else          { g10 = sigf(g10);   g11 = sigf(g11);  }
        sg[j0]      = g00; sg[j1]      = g10;
        sg[NG + j0] = g01; sg[NG + j1] = g11;
        __syncthreads();
        if (tid < HID){
            int u = tid;
            float i0 = sg[u],      ff0 = sg[HID+u],    gg0 = sg[2*HID+u],    o0 = sg[3*HID+u];
            float i1 = sg[NG+u],   ff1 = sg[NG+HID+u], gg1 = sg[NG+2*HID+u], o1 = sg[NG+3*HID+u];
            c0 = fmaf(ff0, c0, i0 * gg0);
            c1 = fmaf(ff1, c1, i1 * gg1);
            float h0v = o0 * tanhf_(c0);
            float h1v = o1 * tanhf_(c1);
            sh[u] = h0v; sh[HID + u] = h1v;
            if (MODE != 2){
                g_hseq[((size_t)t * B_ROWS + r0    ) * HID + u] = h0v;
                g_hseq[((size_t)t * B_ROWS + r0 + 1) * HID + u] = h1v;
            } else if (t == T_STEPS - 1){
                g_hT[(size_t)r0 * HID + u]       = h0v;
                g_hT[(size_t)(r0+1) * HID + u]   = h1v;
            }
        }
        __syncthreads();
    }
}

// ---------------- input-projection GEMM ----------------
// C(M=524288, 512) = hseq(M,128) @ W^T(128,512) + (bih+bhh)
// Block tile 128x128, K chunked by 32. f32x2 paired along K (even/odd lanes),
// horizontal add at epilogue. As/Bs natural layout, stride-36 pad:
//  - a reads broadcast (2 addrs/warp)
//  - b reads conflict-free (col = tx + 16c; bank stride 2 per lane, 8B loads)
__global__ void __launch_bounds__(256, 1)
gemm_xg(const float* __restrict__ W,     // (512,128)
        const float* __restrict__ ba,
        const float* __restrict__ bb)
{
    __shared__ float As[128][36];
    __shared__ float Bs[128][36];
    const int tid = threadIdx.x;
    const int tx = tid & 15, ty = tid >> 4;
    const size_t m0 = (size_t)blockIdx.x * 128;
    const int n0 = blockIdx.y * 128;

    ull acc[8][8];
    #pragma unroll
    for (int r = 0; r < 8; r++)
        #pragma unroll
        for (int c = 0; c < 8; c++) acc[r][c] = 0ULL;

    for (int k0 = 0; k0 < HID; k0 += 32){
        #pragma unroll
        for (int i = 0; i < 4; i++){
            int idx = tid + i * 256;          // float4 index within 128x32 tile
            int m = idx >> 3, k4 = (idx & 7) << 2;
            *(float4*)&As[m][k4] = *(const float4*)&g_hseq[(m0 + m) * HID + k0 + k4];
            *(float4*)&Bs[m][k4] = *(const float4*)&W[(size_t)(n0 + m) * HID + k0 + k4];
        }
        __syncthreads();
        #pragma unroll
        for (int kp = 0; kp < 16; kp++){
            ull ap[8], bp[8];
            #pragma unroll
            for (int r = 0; r < 8; r++) ap[r] = *(const ull*)&As[ty*8 + r][2*kp];
            #pragma unroll
            for (int c = 0; c < 8; c++) bp[c] = *(const ull*)&Bs[tx + 16*c][2*kp];
            #pragma unroll
            for (int r = 0; r < 8; r++)
                #pragma unroll
                for (int c = 0; c < 8; c++)
                    acc[r][c] = ffma2(ap[r], bp[c], acc[r][c]);
        }
        __syncthreads();
    }
    #pragma unroll
    for (int c = 0; c < 8; c++){
        int n = n0 + tx + 16*c;
        float bias = __ldg(ba + n) + __ldg(bb + n);
        #pragma unroll
        for (int r = 0; r < 8; r++){
            float2 v = unpk(acc[r][c]);
            g_xg[(m0 + ty*8 + r) * NG + n] = v.x + v.y + bias;
        }
    }
}

// ---------------- FC head ----------------
__global__ void head_kernel(const float* __restrict__ w1, const float* __restrict__ b1,
                            const float* __restrict__ w2, const float* __restrict__ b2,
                            float* __restrict__ out)
{
    __shared__ float z[64];
    int b = blockIdx.x, u = threadIdx.x;
    const float* h = g_hT + (size_t)b * HID;
    float acc = b1[u];
    const float* w = w1 + (size_t)u * HID;
    #pragma unroll 4
    for (int k = 0; k < HID; k++) acc = fmaf(w[k], h[k], acc);
    z[u] = fmaxf(acc, 0.f);
    __syncthreads();
    if (u < 5){
        float a2 = b2[u];
        const float* ww = w2 + u * 64;
        #pragma unroll 4
        for (int k = 0; k < 64; k++) a2 = fmaf(ww[k], z[k], a2);
        out[b * 5 + u] = a2;
    }
}

// ---------------- launch ----------------
extern "C" void kernel_launch(void* const* d_in, const int* in_sizes, int n_in,
                              void* d_out, int out_size)
{
    const float* x    = (const float*)d_in[0];
    const float* Wih0 = (const float*)d_in[1];
    const float* Whh0 = (const float*)d_in[2];
    const float* bih0 = (const float*)d_in[3];
    const float* bhh0 = (const float*)d_in[4];
    const float* Wih1 = (const float*)d_in[5];
    const float* Whh1 = (const float*)d_in[6];
    const float* bih1 = (const float*)d_in[7];
    const float* bhh1 = (const float*)d_in[8];
    const float* Wih2 = (const float*)d_in[9];
    const float* Whh2 = (const float*)d_in[10];
    const float* bih2 = (const float*)d_in[11];
    const float* bhh2 = (const float*)d_in[12];
    const float* fc1w = (const float*)d_in[13];
    const float* fc1b = (const float*)d_in[14];
    const float* fc2w = (const float*)d_in[15];
    const float* fc2b = (const float*)d_in[16];
    float* out = (float*)d_out;

    // idempotent; executes immediately (not a stream op), safe under capture
    cudaFuncSetAttribute(lstm_rec<0>, cudaFuncAttributeMaxDynamicSharedMemorySize, REC_SMEM);
    cudaFuncSetAttribute(lstm_rec<1>, cudaFuncAttributeMaxDynamicSharedMemorySize, REC_SMEM);
    cudaFuncSetAttribute(lstm_rec<2>, cudaFuncAttributeMaxDynamicSharedMemorySize, REC_SMEM);

    const int M_TILES = (T_STEPS * B_ROWS) / 128;   // 4096

    lstm_rec<0><<<128, 256, REC_SMEM>>>(x, Wih0, bih0, bhh0, Whh0);
    gemm_xg<<<dim3(M_TILES, 4), 256>>>(Wih1, bih1, bhh1);
    lstm_rec<1><<<128, 256, REC_SMEM>>>(nullptr, nullptr, nullptr, nullptr, Whh1);
    gemm_xg<<<dim3(M_TILES, 4), 256>>>(Wih2, bih2, bhh2);
    lstm_rec<2><<<128, 256, REC_SMEM>>>(nullptr, nullptr, nullptr, nullptr, Whh2);
    head_kernel<<<B_ROWS, 64>>>(fc1w, fc1b, fc2w, fc2b, out);
}

// round 5
// speedup vs baseline: 1.2319x; 1.2319x over previous
#include <cuda_runtime.h>

typedef unsigned long long ull;
typedef unsigned int uint;

#define T_STEPS 2048
#define B_ROWS  256
#define HID     128
#define NG      512

// ---------------- scratch (device globals: allocation-free) ----------------
__device__ float g_hseq[(size_t)T_STEPS * B_ROWS * HID];   // 256 MB
__device__ float g_xg[(size_t)T_STEPS * B_ROWS * NG];      // 1 GB
__device__ float g_hT[B_ROWS * HID];

// ---------------- packed f32x2 helpers (sm_100+) ----------------
__device__ __forceinline__ ull pk2(float lo, float hi){
    ull r; asm("mov.b64 %0,{%1,%2};" : "=l"(r) : "f"(lo), "f"(hi)); return r;
}
__device__ __forceinline__ ull ffma2(ull a, ull b, ull c){
    ull d; asm("fma.rn.f32x2 %0,%1,%2,%3;" : "=l"(d) : "l"(a), "l"(b), "l"(c)); return d;
}
__device__ __forceinline__ float2 unpk(ull v){
    float2 r; asm("mov.b64 {%0,%1},%2;" : "=f"(r.x), "=f"(r.y) : "l"(v)); return r;
}
__device__ __forceinline__ float sigf(float x){
    return __fdividef(1.f, 1.f + __expf(-x));
}
__device__ __forceinline__ float tanhf_(float x){
    return 1.f - 2.f * __fdividef(1.f, __expf(2.f * x) + 1.f);
}

// ================= recurrent kernel =================
// 128 CTAs x 256 threads. CTA b owns batch rows 2b, 2b+1.
// Thread tid owns gate rows j0=tid (i|f) and j1=tid+256 (g|o).
// Whh cols [0,80) in regs (40 f32x2/row), cols [80,128) in SMEM.
constexpr int KREGP = 40;
constexpr int KSM4  = 12;
constexpr int REC_SMEM_BASE = (KSM4*NG*4 + 2*HID + 2*NG) * 4;          // 103424
constexpr int REC_SMEM0     = REC_SMEM_BASE + 2*T_STEPS*4;             // +16KB x cache

template<int MODE>   // 0: layer0 (x folded, writes hseq) 1: mid 2: last (writes hT)
__global__ void __launch_bounds__(256, 1)
lstm_rec(const float* __restrict__ xin,
         const float* __restrict__ wih,
         const float* __restrict__ bih,
         const float* __restrict__ bhh,
         const float* __restrict__ Whh)
{
    extern __shared__ float sm[];
    float4* ws = (float4*)sm;             // [KSM4][NG] weight tail
    float*  sh = sm + KSM4*NG*4;          // [2][HID] hidden state
    float*  sg = sh + 2*HID;              // [2][NG]  activated gates
    float*  sx = sg + 2*NG;               // MODE0: [2][T] input cache

    const int tid = threadIdx.x;
    const int j0 = tid, j1 = tid + 256;
    const int r0 = blockIdx.x * 2;

    // one-time weight load
    ull w0[KREGP], w1[KREGP];
    {
        const float* p0 = Whh + (size_t)j0 * HID;
        const float* p1 = Whh + (size_t)j1 * HID;
        #pragma unroll
        for (int p = 0; p < KREGP; p++){
            w0[p] = *(const ull*)(p0 + 2*p);
            w1[p] = *(const ull*)(p1 + 2*p);
        }
        #pragma unroll
        for (int q = 0; q < KSM4; q++){
            ws[q*NG + j0] = *(const float4*)(p0 + 2*KREGP + 4*q);
            ws[q*NG + j1] = *(const float4*)(p1 + 2*KREGP + 4*q);
        }
    }
    float wi0 = 0.f, wi1 = 0.f, bb0 = 0.f, bb1 = 0.f;
    if (MODE == 0){
        wi0 = wih[j0]; wi1 = wih[j1];
        bb0 = bih[j0] + bhh[j0]; bb1 = bih[j1] + bhh[j1];
        // cache the two input rows in smem (coalesced)
        for (int i = tid; i < 2*T_STEPS; i += 256){
            int row = i >> 11, t = i & (T_STEPS-1);
            sx[i] = xin[(size_t)(r0 + row) * T_STEPS + t];
        }
    }
    if (tid < HID){ sh[tid] = 0.f; sh[HID + tid] = 0.f; }
    float cc = 0.f;                       // per-thread cell state (row=tid>>7, u=tid&127)
    __syncthreads();

    // prefetch t=0 gate inputs
    float nx00, nx01, nx10, nx11;
    if (MODE != 0){
        const float* xg = g_xg + (size_t)r0 * NG;
        nx00 = __ldcs(xg + j0);      nx10 = __ldcs(xg + j1);
        nx01 = __ldcs(xg + NG + j0); nx11 = __ldcs(xg + NG + j1);
    }

    #pragma unroll 1
    for (int t = 0; t < T_STEPS; t++){
        float in00, in01, in10, in11;
        if (MODE == 0){
            float xv0 = sx[t], xv1 = sx[T_STEPS + t];
            in00 = fmaf(xv0, wi0, bb0); in01 = fmaf(xv1, wi0, bb0);
            in10 = fmaf(xv0, wi1, bb1); in11 = fmaf(xv1, wi1, bb1);
        } else {
            in00 = nx00; in01 = nx01; in10 = nx10; in11 = nx11;
            int tn = (t + 1 < T_STEPS) ? t + 1 : t;
            const float* xgn = g_xg + ((size_t)tn * B_ROWS + r0) * NG;
            nx00 = __ldcs(xgn + j0);      nx10 = __ldcs(xgn + j1);
            nx01 = __ldcs(xgn + NG + j0); nx11 = __ldcs(xgn + NG + j1);
        }
        ull a00 = pk2(in00, 0.f), a01 = pk2(in01, 0.f);
        ull a10 = pk2(in10, 0.f), a11 = pk2(in11, 0.f);

        const ulonglong2* h0 = (const ulonglong2*)sh;
        const ulonglong2* h1 = (const ulonglong2*)(sh + HID);
        #pragma unroll
        for (int p = 0; p < KREGP/2; p++){
            ulonglong2 hp0 = h0[p], hp1 = h1[p];
            a00 = ffma2(w0[2*p],   hp0.x, a00);
            a00 = ffma2(w0[2*p+1], hp0.y, a00);
            a01 = ffma2(w0[2*p],   hp1.x, a01);
            a01 = ffma2(w0[2*p+1], hp1.y, a01);
            a10 = ffma2(w1[2*p],   hp0.x, a10);
            a10 = ffma2(w1[2*p+1], hp0.y, a10);
            a11 = ffma2(w1[2*p],   hp1.x, a11);
            a11 = ffma2(w1[2*p+1], hp1.y, a11);
        }
        #pragma unroll
        for (int q = 0; q < KSM4; q++){
            float4 v0 = ws[q*NG + j0];
            float4 v1 = ws[q*NG + j1];
            ulonglong2 hq0 = h0[KREGP/2 + q];
            ulonglong2 hq1 = h1[KREGP/2 + q];
            ull w0a = pk2(v0.x, v0.y), w0b = pk2(v0.z, v0.w);
            ull w1a = pk2(v1.x, v1.y), w1b = pk2(v1.z, v1.w);
            a00 = ffma2(w0a, hq0.x, a00); a00 = ffma2(w0b, hq0.y, a00);
            a01 = ffma2(w0a, hq1.x, a01); a01 = ffma2(w0b, hq1.y, a01);
            a10 = ffma2(w1a, hq0.x, a10); a10 = ffma2(w1b, hq0.y, a10);
            a11 = ffma2(w1a, hq1.x, a11); a11 = ffma2(w1b, hq1.y, a11);
        }
        float2 f00 = unpk(a00), f01 = unpk(a01), f10 = unpk(a10), f11 = unpk(a11);
        float g00 = f00.x + f00.y, g01 = f01.x + f01.y;
        float g10 = f10.x + f10.y, g11 = f11.x + f11.y;
        g00 = sigf(g00); g01 = sigf(g01);
        if (tid < 128){ g10 = tanhf_(g10); g11 = tanhf_(g11); }
        else          { g10 = sigf(g10);   g11 = sigf(g11);  }
        sg[j0]      = g00; sg[j1]      = g10;
        sg[NG + j0] = g01; sg[NG + j1] = g11;
        __syncthreads();
        {
            int row = tid >> 7, u = tid & 127;
            const float* sgr = sg + row * NG;
            float iv = sgr[u], fv = sgr[HID+u], gv = sgr[2*HID+u], ov = sgr[3*HID+u];
            cc = fmaf(fv, cc, iv * gv);
            float hv = ov * tanhf_(cc);
            sh[row * HID + u] = hv;
            if (MODE != 2){
                g_hseq[((size_t)t * B_ROWS + r0 + row) * HID + u] = hv;
            } else if (t == T_STEPS - 1){
                g_hT[(size_t)(r0 + row) * HID + u] = hv;
            }
        }
        __syncthreads();
    }
}

// ================= input-projection GEMM v2 =================
// C(M=524288,512) = hseq(M,128) @ W^T + bias.  Persistent CTAs: grid (37,4).
// B tile (128 n-rows x 128 k) resident in smem whole kernel, pair-transposed
// [kp][n] float2 (row stride 129 -> conflict-free). A tiles natural [m][k],
// double-buffered via cp.async (contiguous 64KB blocks of g_hseq).
constexpr int M_TILES   = (T_STEPS * B_ROWS) / 128;     // 4096
constexpr int GRID_X    = 37;
constexpr int A_TILE_F  = 128 * 128;                    // floats
constexpr int BSP_F2    = 64 * 129;                     // float2 slots
constexpr int GEMM_SMEM = (2 * A_TILE_F) * 4 + BSP_F2 * 8;   // 197120 B

__global__ void __launch_bounds__(256, 1)
gemm_xg(const float* __restrict__ W,
        const float* __restrict__ ba,
        const float* __restrict__ bb)
{
    extern __shared__ float sm[];
    float*  As  = sm;                       // [2][128][128]
    float2* Bsp = (float2*)(sm + 2 * A_TILE_F);  // [64][129]

    const int tid = threadIdx.x;
    const int tx = tid & 15, ty = tid >> 4;
    const int n0 = blockIdx.y * 128;

    // ---- load B tile once, pair-transposed ----
    #pragma unroll
    for (int i = 0; i < 16; i++){
        int idx = tid + i * 256;            // float4 id over [128 rows][32 chunks]
        int n = idx >> 5, k4 = (idx & 31) << 2;
        float4 v = *(const float4*)&W[(size_t)(n0 + n) * HID + k4];
        int kp = k4 >> 1;
        Bsp[kp * 129 + n]       = make_float2(v.x, v.y);
        Bsp[(kp + 1) * 129 + n] = make_float2(v.z, v.w);
    }

    // ---- per-thread bias (n fixed for whole kernel) ----
    float bias[8];
    #pragma unroll
    for (int c = 0; c < 8; c++){
        int n = n0 + tx + 16*c;
        bias[c] = __ldg(ba + n) + __ldg(bb + n);
    }

    uint sA = (uint)__cvta_generic_to_shared(As);

    auto issue = [&](int mt, int buf){
        const float* src = g_hseq + (size_t)mt * A_TILE_F;
        uint dst = sA + buf * (A_TILE_F * 4);
        #pragma unroll
        for (int i = 0; i < 16; i++){
            int idx = tid + i * 256;
            asm volatile("cp.async.cg.shared.global [%0], [%1], 16;\n"
                         :: "r"(dst + idx * 16), "l"(src + idx * 4));
        }
        asm volatile("cp.async.commit_group;\n" ::: "memory");
    };

    int mt = blockIdx.x;
    if (mt < M_TILES) issue(mt, 0);
    int buf = 0;

    #pragma unroll 1
    for (; mt < M_TILES; mt += GRID_X){
        int nxt = mt + GRID_X;
        if (nxt < M_TILES) issue(nxt, buf ^ 1);
        if (nxt < M_TILES) asm volatile("cp.async.wait_group 1;\n" ::: "memory");
        else               asm volatile("cp.async.wait_group 0;\n" ::: "memory");
        __syncthreads();

        const float* Ab = As + buf * A_TILE_F;
        ull acc[8][8];
        #pragma unroll
        for (int r = 0; r < 8; r++)
            #pragma unroll
            for (int c = 0; c < 8; c++) acc[r][c] = 0ULL;

        #pragma unroll 4
        for (int kp = 0; kp < 64; kp++){
            ull ap[8], bp[8];
            #pragma unroll
            for (int r = 0; r < 8; r++)
                ap[r] = *(const ull*)&Ab[(ty*8 + r) * 128 + 2*kp];
            #pragma unroll
            for (int c = 0; c < 8; c++)
                bp[c] = *(const ull*)&Bsp[kp * 129 + tx + 16*c];
            #pragma unroll
            for (int r = 0; r < 8; r++)
                #pragma unroll
                for (int c = 0; c < 8; c++)
                    acc[r][c] = ffma2(ap[r], bp[c], acc[r][c]);
        }

        #pragma unroll
        for (int c = 0; c < 8; c++){
            int n = tx + 16*c;
            #pragma unroll
            for (int r = 0; r < 8; r++){
                float2 v = unpk(acc[r][c]);
                g_xg[((size_t)mt * 128 + ty*8 + r) * NG + n0 + n] = v.x + v.y + bias[c];
            }
        }
        __syncthreads();
        buf ^= 1;
    }
}

// ================= FC head =================
__global__ void head_kernel(const float* __restrict__ w1, const float* __restrict__ b1,
                            const float* __restrict__ w2, const float* __restrict__ b2,
                            float* __restrict__ out)
{
    __shared__ float z[64];
    int b = blockIdx.x, u = threadIdx.x;
    const float* h = g_hT + (size_t)b * HID;
    float acc = b1[u];
    const float* w = w1 + (size_t)u * HID;
    #pragma unroll 4
    for (int k = 0; k < HID; k++) acc = fmaf(w[k], h[k], acc);
    z[u] = fmaxf(acc, 0.f);
    __syncthreads();
    if (u < 5){
        float a2 = b2[u];
        const float* ww = w2 + u * 64;
        #pragma unroll 4
        for (int k = 0; k < 64; k++) a2 = fmaf(ww[k], z[k], a2);
        out[b * 5 + u] = a2;
    }
}

// ================= launch =================
extern "C" void kernel_launch(void* const* d_in, const int* in_sizes, int n_in,
                              void* d_out, int out_size)
{
    const float* x    = (const float*)d_in[0];
    const float* Wih0 = (const float*)d_in[1];
    const float* Whh0 = (const float*)d_in[2];
    const float* bih0 = (const float*)d_in[3];
    const float* bhh0 = (const float*)d_in[4];
    const float* Wih1 = (const float*)d_in[5];
    const float* Whh1 = (const float*)d_in[6];
    const float* bih1 = (const float*)d_in[7];
    const float* bhh1 = (const float*)d_in[8];
    const float* Wih2 = (const float*)d_in[9];
    const float* Whh2 = (const float*)d_in[10];
    const float* bih2 = (const float*)d_in[11];
    const float* bhh2 = (const float*)d_in[12];
    const float* fc1w = (const float*)d_in[13];
    const float* fc1b = (const float*)d_in[14];
    const float* fc2w = (const float*)d_in[15];
    const float* fc2b = (const float*)d_in[16];
    float* out = (float*)d_out;

    cudaFuncSetAttribute(lstm_rec<0>, cudaFuncAttributeMaxDynamicSharedMemorySize, REC_SMEM0);
    cudaFuncSetAttribute(lstm_rec<1>, cudaFuncAttributeMaxDynamicSharedMemorySize, REC_SMEM_BASE);
    cudaFuncSetAttribute(lstm_rec<2>, cudaFuncAttributeMaxDynamicSharedMemorySize, REC_SMEM_BASE);
    cudaFuncSetAttribute(gemm_xg,     cudaFuncAttributeMaxDynamicSharedMemorySize, GEMM_SMEM);

    lstm_rec<0><<<128, 256, REC_SMEM0>>>(x, Wih0, bih0, bhh0, Whh0);
    gemm_xg<<<dim3(GRID_X, 4), 256, GEMM_SMEM>>>(Wih1, bih1, bhh1);
    lstm_rec<1><<<128, 256, REC_SMEM_BASE>>>(nullptr, nullptr, nullptr, nullptr, Whh1);
    gemm_xg<<<dim3(GRID_X, 4), 256, GEMM_SMEM>>>(Wih2, bih2, bhh2);
    lstm_rec<2><<<128, 256, REC_SMEM_BASE>>>(nullptr, nullptr, nullptr, nullptr, Whh2);
    head_kernel<<<B_ROWS, 64>>>(fc1w, fc1b, fc2w, fc2b, out);
}

// round 6
// speedup vs baseline: 1.2354x; 1.0028x over previous
#include <cuda_runtime.h>

typedef unsigned long long ull;
typedef unsigned int uint;

#define T_STEPS 2048
#define B_ROWS  256
#define HID     128
#define NG      512

// ---------------- scratch (device globals: allocation-free) ----------------
__device__ float g_hseq[(size_t)T_STEPS * B_ROWS * HID];   // 256 MB
__device__ float g_xg[(size_t)T_STEPS * B_ROWS * NG];      // 1 GB
__device__ float g_hT[B_ROWS * HID];

// ---------------- packed f32x2 helpers (sm_100+) ----------------
__device__ __forceinline__ ull pk2(float lo, float hi){
    ull r; asm("mov.b64 %0,{%1,%2};" : "=l"(r) : "f"(lo), "f"(hi)); return r;
}
__device__ __forceinline__ ull ffma2(ull a, ull b, ull c){
    ull d; asm("fma.rn.f32x2 %0,%1,%2,%3;" : "=l"(d) : "l"(a), "l"(b), "l"(c)); return d;
}
__device__ __forceinline__ float2 unpk(ull v){
    float2 r; asm("mov.b64 {%0,%1},%2;" : "=f"(r.x), "=f"(r.y) : "l"(v)); return r;
}
__device__ __forceinline__ float sigf(float x){
    return __fdividef(1.f, 1.f + __expf(-x));
}
__device__ __forceinline__ float tanhf_(float x){
    return 1.f - 2.f * __fdividef(1.f, __expf(2.f * x) + 1.f);
}

// ================= recurrent kernel =================
// 128 CTAs x 256 threads. CTA b owns batch rows 2b, 2b+1.
// Thread tid owns gate rows j0=tid (i|f) and j1=tid+256 (g|o).
// Whh cols [0,80) in regs (40 f32x2/row), cols [80,128) in SMEM.
constexpr int KREGP = 40;
constexpr int KSM4  = 12;
constexpr int REC_SMEM_BASE = (KSM4*NG*4 + 2*HID + 2*NG) * 4;          // 103424
constexpr int REC_SMEM0     = REC_SMEM_BASE + 2*T_STEPS*4;             // +16KB x cache

template<int MODE>   // 0: layer0 (x folded, writes hseq) 1: mid 2: last (writes hT)
__global__ void __launch_bounds__(256, 1)
lstm_rec(const float* __restrict__ xin,
         const float* __restrict__ wih,
         const float* __restrict__ bih,
         const float* __restrict__ bhh,
         const float* __restrict__ Whh)
{
    extern __shared__ float sm[];
    float4* ws = (float4*)sm;             // [KSM4][NG] weight tail
    float*  sh = sm + KSM4*NG*4;          // [2][HID] hidden state
    float*  sg = sh + 2*HID;              // [2][NG]  activated gates
    float*  sx = sg + 2*NG;               // MODE0: [2][T] input cache

    const int tid = threadIdx.x;
    const int j0 = tid, j1 = tid + 256;
    const int r0 = blockIdx.x * 2;

    // one-time weight load
    ull w0[KREGP], w1[KREGP];
    {
        const float* p0 = Whh + (size_t)j0 * HID;
        const float* p1 = Whh + (size_t)j1 * HID;
        #pragma unroll
        for (int p = 0; p < KREGP; p++){
            w0[p] = *(const ull*)(p0 + 2*p);
            w1[p] = *(const ull*)(p1 + 2*p);
        }
        #pragma unroll
        for (int q = 0; q < KSM4; q++){
            ws[q*NG + j0] = *(const float4*)(p0 + 2*KREGP + 4*q);
            ws[q*NG + j1] = *(const float4*)(p1 + 2*KREGP + 4*q);
        }
    }
    float wi0 = 0.f, wi1 = 0.f, bb0 = 0.f, bb1 = 0.f;
    if (MODE == 0){
        wi0 = wih[j0]; wi1 = wih[j1];
        bb0 = bih[j0] + bhh[j0]; bb1 = bih[j1] + bhh[j1];
        // cache the two input rows in smem (coalesced)
        for (int i = tid; i < 2*T_STEPS; i += 256){
            int row = i >> 11, t = i & (T_STEPS-1);
            sx[i] = xin[(size_t)(r0 + row) * T_STEPS + t];
        }
    }
    if (tid < HID){ sh[tid] = 0.f; sh[HID + tid] = 0.f; }
    float cc = 0.f;                       // per-thread cell state (row=tid>>7, u=tid&127)
    __syncthreads();

    // prefetch t=0 gate inputs
    float nx00, nx01, nx10, nx11;
    if (MODE != 0){
        const float* xg = g_xg + (size_t)r0 * NG;
        nx00 = __ldcs(xg + j0);      nx10 = __ldcs(xg + j1);
        nx01 = __ldcs(xg + NG + j0); nx11 = __ldcs(xg + NG + j1);
    }

    #pragma unroll 1
    for (int t = 0; t < T_STEPS; t++){
        float in00, in01, in10, in11;
        if (MODE == 0){
            float xv0 = sx[t], xv1 = sx[T_STEPS + t];
            in00 = fmaf(xv0, wi0, bb0); in01 = fmaf(xv1, wi0, bb0);
            in10 = fmaf(xv0, wi1, bb1); in11 = fmaf(xv1, wi1, bb1);
        } else {
            in00 = nx00; in01 = nx01; in10 = nx10; in11 = nx11;
            int tn = (t + 1 < T_STEPS) ? t + 1 : t;
            const float* xgn = g_xg + ((size_t)tn * B_ROWS + r0) * NG;
            nx00 = __ldcs(xgn + j0);      nx10 = __ldcs(xgn + j1);
            nx01 = __ldcs(xgn + NG + j0); nx11 = __ldcs(xgn + NG + j1);
        }
        ull a00 = pk2(in00, 0.f), a01 = pk2(in01, 0.f);
        ull a10 = pk2(in10, 0.f), a11 = pk2(in11, 0.f);

        const ulonglong2* h0 = (const ulonglong2*)sh;
        const ulonglong2* h1 = (const ulonglong2*)(sh + HID);
        #pragma unroll
        for (int p = 0; p < KREGP/2; p++){
            ulonglong2 hp0 = h0[p], hp1 = h1[p];
            a00 = ffma2(w0[2*p],   hp0.x, a00);
            a00 = ffma2(w0[2*p+1], hp0.y, a00);
            a01 = ffma2(w0[2*p],   hp1.x, a01);
            a01 = ffma2(w0[2*p+1], hp1.y, a01);
            a10 = ffma2(w1[2*p],   hp0.x, a10);
            a10 = ffma2(w1[2*p+1], hp0.y, a10);
            a11 = ffma2(w1[2*p],   hp1.x, a11);
            a11 = ffma2(w1[2*p+1], hp1.y, a11);
        }
        #pragma unroll
        for (int q = 0; q < KSM4; q++){
            float4 v0 = ws[q*NG + j0];
            float4 v1 = ws[q*NG + j1];
            ulonglong2 hq0 = h0[KREGP/2 + q];
            ulonglong2 hq1 = h1[KREGP/2 + q];
            ull w0a = pk2(v0.x, v0.y), w0b = pk2(v0.z, v0.w);
            ull w1a = pk2(v1.x, v1.y), w1b = pk2(v1.z, v1.w);
            a00 = ffma2(w0a, hq0.x, a00); a00 = ffma2(w0b, hq0.y, a00);
            a01 = ffma2(w0a, hq1.x, a01); a01 = ffma2(w0b, hq1.y, a01);
            a10 = ffma2(w1a, hq0.x, a10); a10 = ffma2(w1b, hq0.y, a10);
            a11 = ffma2(w1a, hq1.x, a11); a11 = ffma2(w1b, hq1.y, a11);
        }
        float2 f00 = unpk(a00), f01 = unpk(a01), f10 = unpk(a10), f11 = unpk(a11);
        float g00 = f00.x + f00.y, g01 = f01.x + f01.y;
        float g10 = f10.x + f10.y, g11 = f11.x + f11.y;
        g00 = sigf(g00); g01 = sigf(g01);
        if (tid < 128){ g10 = tanhf_(g10); g11 = tanhf_(g11); }
        else          { g10 = sigf(g10);   g11 = sigf(g11);  }
        sg[j0]      = g00; sg[j1]      = g10;
        sg[NG + j0] = g01; sg[NG + j1] = g11;
        __syncthreads();
        {
            int row = tid >> 7, u = tid & 127;
            const float* sgr = sg + row * NG;
            float iv = sgr[u], fv = sgr[HID+u], gv = sgr[2*HID+u], ov = sgr[3*HID+u];
            cc = fmaf(fv, cc, iv * gv);
            float hv = ov * tanhf_(cc);
            sh[row * HID + u] = hv;
            if (MODE != 2){
                g_hseq[((size_t)t * B_ROWS + r0 + row) * HID + u] = hv;
            } else if (t == T_STEPS - 1){
                g_hT[(size_t)(r0 + row) * HID + u] = hv;
            }
        }
        __syncthreads();
    }
}

// ================= input-projection GEMM v2 =================
// C(M=524288,512) = hseq(M,128) @ W^T + bias.  Persistent CTAs: grid (37,4).
// B tile (128 n-rows x 128 k) resident in smem whole kernel, pair-transposed
// [kp][n] float2 (row stride 129 -> conflict-free). A tiles natural [m][k],
// double-buffered via cp.async (contiguous 64KB blocks of g_hseq).
constexpr int M_TILES   = (T_STEPS * B_ROWS) / 128;     // 4096
constexpr int GRID_X    = 37;
constexpr int A_TILE_F  = 128 * 128;                    // floats
constexpr int BSP_F2    = 64 * 129;                     // float2 slots
constexpr int GEMM_SMEM = (2 * A_TILE_F) * 4 + BSP_F2 * 8;   // 197120 B

__global__ void __launch_bounds__(256, 1)
gemm_xg(const float* __restrict__ W,
        const float* __restrict__ ba,
        const float* __restrict__ bb)
{
    extern __shared__ float sm[];
    float*  As  = sm;                       // [2][128][128]
    float2* Bsp = (float2*)(sm + 2 * A_TILE_F);  // [64][129]

    const int tid = threadIdx.x;
    const int tx = tid & 15, ty = tid >> 4;
    const int n0 = blockIdx.y * 128;

    // ---- load B tile once, pair-transposed ----
    #pragma unroll
    for (int i = 0; i < 16; i++){
        int idx = tid + i * 256;            // float4 id over [128 rows][32 chunks]
        int n = idx >> 5, k4 = (idx & 31) << 2;
        float4 v = *(const float4*)&W[(size_t)(n0 + n) * HID + k4];
        int kp = k4 >> 1;
        Bsp[kp * 129 + n]       = make_float2(v.x, v.y);
        Bsp[(kp + 1) * 129 + n] = make_float2(v.z, v.w);
    }

    // ---- per-thread bias (n fixed for whole kernel) ----
    float bias[8];
    #pragma unroll
    for (int c = 0; c < 8; c++){
        int n = n0 + tx + 16*c;
        bias[c] = __ldg(ba + n) + __ldg(bb + n);
    }

    uint sA = (uint)__cvta_generic_to_shared(As);

    auto issue = [&](int mt, int buf){
        const float* src = g_hseq + (size_t)mt * A_TILE_F;
        uint dst = sA + buf * (A_TILE_F * 4);
        #pragma unroll
        for (int i = 0; i < 16; i++){
            int idx = tid + i * 256;
            asm volatile("cp.async.cg.shared.global [%0], [%1], 16;\n"
                         :: "r"(dst + idx * 16), "l"(src + idx * 4));
        }
        asm volatile("cp.async.commit_group;\n" ::: "memory");
    };

    int mt = blockIdx.x;
    if (mt < M_TILES) issue(mt, 0);
    int buf = 0;

    #pragma unroll 1
    for (; mt < M_TILES; mt += GRID_X){
        int nxt = mt + GRID_X;
        if (nxt < M_TILES) issue(nxt, buf ^ 1);
        if (nxt < M_TILES) asm volatile("cp.async.wait_group 1;\n" ::: "memory");
        else               asm volatile("cp.async.wait_group 0;\n" ::: "memory");
        __syncthreads();

        const float* Ab = As + buf * A_TILE_F;
        ull acc[8][8];
        #pragma unroll
        for (int r = 0; r < 8; r++)
            #pragma unroll
            for (int c = 0; c < 8; c++) acc[r][c] = 0ULL;

        #pragma unroll 4
        for (int kp = 0; kp < 64; kp++){
            ull ap[8], bp[8];
            #pragma unroll
            for (int r = 0; r < 8; r++)
                ap[r] = *(const ull*)&Ab[(ty*8 + r) * 128 + 2*kp];
            #pragma unroll
            for (int c = 0; c < 8; c++)
                bp[c] = *(const ull*)&Bsp[kp * 129 + tx + 16*c];
            #pragma unroll
            for (int r = 0; r < 8; r++)
                #pragma unroll
                for (int c = 0; c < 8; c++)
                    acc[r][c] = ffma2(ap[r], bp[c], acc[r][c]);
        }

        #pragma unroll
        for (int c = 0; c < 8; c++){
            int n = tx + 16*c;
            #pragma unroll
            for (int r = 0; r < 8; r++){
                float2 v = unpk(acc[r][c]);
                g_xg[((size_t)mt * 128 + ty*8 + r) * NG + n0 + n] = v.x + v.y + bias[c];
            }
        }
        __syncthreads();
        buf ^= 1;
    }
}

// ================= FC head =================
__global__ void head_kernel(const float* __restrict__ w1, const float* __restrict__ b1,
                            const float* __restrict__ w2, const float* __restrict__ b2,
                            float* __restrict__ out)
{
    __shared__ float z[64];
    int b = blockIdx.x, u = threadIdx.x;
    const float* h = g_hT + (size_t)b * HID;
    float acc = b1[u];
    const float* w = w1 + (size_t)u * HID;
    #pragma unroll 4
    for (int k = 0; k < HID; k++) acc = fmaf(w[k], h[k], acc);
    z[u] = fmaxf(acc, 0.f);
    __syncthreads();
    if (u < 5){
        float a2 = b2[u];
        const float* ww = w2 + u * 64;
        #pragma unroll 4
        for (int k = 0; k < 64; k++) a2 = fmaf(ww[k], z[k], a2);
        out[b * 5 + u] = a2;
    }
}

// ================= launch =================
extern "C" void kernel_launch(void* const* d_in, const int* in_sizes, int n_in,
                              void* d_out, int out_size)
{
    const float* x    = (const float*)d_in[0];
    const float* Wih0 = (const float*)d_in[1];
    const float* Whh0 = (const float*)d_in[2];
    const float* bih0 = (const float*)d_in[3];
    const float* bhh0 = (const float*)d_in[4];
    const float* Wih1 = (const float*)d_in[5];
    const float* Whh1 = (const float*)d_in[6];
    const float* bih1 = (const float*)d_in[7];
    const float* bhh1 = (const float*)d_in[8];
    const float* Wih2 = (const float*)d_in[9];
    const float* Whh2 = (const float*)d_in[10];
    const float* bih2 = (const float*)d_in[11];
    const float* bhh2 = (const float*)d_in[12];
    const float* fc1w = (const float*)d_in[13];
    const float* fc1b = (const float*)d_in[14];
    const float* fc2w = (const float*)d_in[15];
    const float* fc2b = (const float*)d_in[16];
    float* out = (float*)d_out;

    cudaFuncSetAttribute(lstm_rec<0>, cudaFuncAttributeMaxDynamicSharedMemorySize, REC_SMEM0);
    cudaFuncSetAttribute(lstm_rec<1>, cudaFuncAttributeMaxDynamicSharedMemorySize, REC_SMEM_BASE);
    cudaFuncSetAttribute(lstm_rec<2>, cudaFuncAttributeMaxDynamicSharedMemorySize, REC_SMEM_BASE);
    cudaFuncSetAttribute(gemm_xg,     cudaFuncAttributeMaxDynamicSharedMemorySize, GEMM_SMEM);

    lstm_rec<0><<<128, 256, REC_SMEM0>>>(x, Wih0, bih0, bhh0, Whh0);
    gemm_xg<<<dim3(GRID_X, 4), 256, GEMM_SMEM>>>(Wih1, bih1, bhh1);
    lstm_rec<1><<<128, 256, REC_SMEM_BASE>>>(nullptr, nullptr, nullptr, nullptr, Whh1);
    gemm_xg<<<dim3(GRID_X, 4), 256, GEMM_SMEM>>>(Wih2, bih2, bhh2);
    lstm_rec<2><<<128, 256, REC_SMEM_BASE>>>(nullptr, nullptr, nullptr, nullptr, Whh2);
    head_kernel<<<B_ROWS, 64>>>(fc1w, fc1b, fc2w, fc2b, out);
}